// round 1
// baseline (speedup 1.0000x reference)
#include <cuda_runtime.h>
#include <cstdint>

// Problem constants (fixed by the dataset).
#define BB 8
#define LL 80000
#define DD 128
#define TT 64
#define NCHUNK (LL / TT)   // 1250

// Scratch (no cudaMalloc allowed): ~20.5 MB total.
__device__ float  d_params[6 * DD];              // zr, zi, cr, ci, zTr, zTi (SoA)
__device__ float2 d_F[BB * NCHUNK * DD];         // per-chunk local contribution
__device__ float2 d_S[BB * NCHUNK * DD];         // per-chunk entry state H[jT-1]

// ---------------------------------------------------------------------------
// K0: derive per-filter parameters in double precision (runs once, 128 thr).
// ---------------------------------------------------------------------------
__global__ void k0_params(const float* __restrict__ omega,
                          const float* __restrict__ alpha_raw,
                          const float* __restrict__ b_log_mag,
                          const float* __restrict__ b_phase) {
    int d = threadIdx.x;
    if (d >= DD) return;
    double ar    = (double)alpha_raw[d];
    double alpha = -log1p(exp(ar));              // -softplus
    double a     = exp(alpha);
    double w     = (double)omega[d];
    double zr    = a * cos(w);
    double zi    = a * sin(w);
    double bmag  = exp((double)b_log_mag[d]);
    double ph    = (double)b_phase[d];
    double cr    = bmag * cos(ph);
    double ci    = bmag * sin(ph);
    double aT    = exp(alpha * (double)TT);
    double wT    = w * (double)TT;
    double zTr   = aT * cos(wT);
    double zTi   = aT * sin(wT);
    d_params[0 * DD + d] = (float)zr;
    d_params[1 * DD + d] = (float)zi;
    d_params[2 * DD + d] = (float)cr;
    d_params[3 * DD + d] = (float)ci;
    d_params[4 * DD + d] = (float)zTr;
    d_params[5 * DD + d] = (float)zTi;
}

// ---------------------------------------------------------------------------
// K1: per (b, chunk): local recurrence from zero state -> F_j = c * acc.
// Block = 128 threads (one per d). acc = z*acc + x over the 64 chunk samples.
// ---------------------------------------------------------------------------
__global__ void k1_localF(const float* __restrict__ x) {
    int blk = blockIdx.x;
    int b = blk / NCHUNK;
    int j = blk % NCHUNK;
    int d = threadIdx.x;

    __shared__ float sx[TT];
    if (d < TT) sx[d] = x[(size_t)b * LL + (size_t)j * TT + d];
    __syncthreads();

    float zr = d_params[0 * DD + d];
    float zi = d_params[1 * DD + d];
    float cr = d_params[2 * DD + d];
    float ci = d_params[3 * DD + d];

    float ar = 0.f, ai = 0.f;
#pragma unroll 8
    for (int u = 0; u < TT; ++u) {
        float xu = sx[u];
        float nr = fmaf(zr, ar, fmaf(-zi, ai, xu));
        float ni = fmaf(zr, ai, zi * ar);
        ar = nr; ai = ni;
    }
    float Fr = fmaf(cr, ar, -ci * ai);
    float Fi = fmaf(cr, ai,  ci * ar);
    d_F[((size_t)b * NCHUNK + j) * DD + d] = make_float2(Fr, Fi);
}

// ---------------------------------------------------------------------------
// K2: sequential scan over chunks: S_{j+1} = z^T * S_j + F_j.
// Grid = B blocks x 128 threads (thread = d). Coalesced float2 ld/st.
// ---------------------------------------------------------------------------
__global__ void k2_scan() {
    int b = blockIdx.x;
    int d = threadIdx.x;
    float zTr = d_params[4 * DD + d];
    float zTi = d_params[5 * DD + d];

    const float2* __restrict__ Fp = d_F + (size_t)b * NCHUNK * DD + d;
    float2* __restrict__       Sp = d_S + (size_t)b * NCHUNK * DD + d;

    float sr = 0.f, si = 0.f;
    for (int j = 0; j < NCHUNK; ++j) {
        Sp[(size_t)j * DD] = make_float2(sr, si);
        float2 f = Fp[(size_t)j * DD];
        float nr = fmaf(zTr, sr, fmaf(-zTi, si, f.x));
        float ni = fmaf(zTr, si, fmaf( zTi, sr, f.y));
        sr = nr; si = ni;
    }
}

// ---------------------------------------------------------------------------
// K3: main. Per (b, chunk): seed H = S_j, run recurrence over 64 samples,
// emit power = |H|^2 each step. Warp writes 128B contiguous rows (coalesced).
// ---------------------------------------------------------------------------
__global__ void k3_main(const float* __restrict__ x, float* __restrict__ out) {
    int blk = blockIdx.x;
    int b = blk / NCHUNK;
    int j = blk % NCHUNK;
    int d = threadIdx.x;

    __shared__ float sx[TT];
    if (d < TT) sx[d] = x[(size_t)b * LL + (size_t)j * TT + d];
    __syncthreads();

    float zr = d_params[0 * DD + d];
    float zi = d_params[1 * DD + d];
    float cr = d_params[2 * DD + d];
    float ci = d_params[3 * DD + d];

    float2 s = d_S[((size_t)b * NCHUNK + j) * DD + d];
    float hr = s.x, hi = s.y;

    float* __restrict__ o = out + ((size_t)b * LL + (size_t)j * TT) * DD + d;
#pragma unroll 8
    for (int u = 0; u < TT; ++u) {
        float xu = sx[u];
        float nr = fmaf(zr, hr, fmaf(-zi, hi, cr * xu));
        float ni = fmaf(zr, hi, fmaf( zi, hr, ci * xu));
        hr = nr; hi = ni;
        o[(size_t)u * DD] = fmaf(hr, hr, hi * hi);
    }
}

// ---------------------------------------------------------------------------
// Launch. Inputs (metadata order): x, omega, alpha_raw, b_log_mag, b_phase, K.
// K (truncation length) is intentionally ignored: the neglected tail has
// magnitude e^{-softplus(alpha_raw)*K} ~ 1e-5 relative, << 1e-3 tolerance.
// ---------------------------------------------------------------------------
extern "C" void kernel_launch(void* const* d_in, const int* in_sizes, int n_in,
                              void* d_out, int out_size) {
    const float* x          = (const float*)d_in[0];
    const float* omega      = (const float*)d_in[1];
    const float* alpha_raw  = (const float*)d_in[2];
    const float* b_log_mag  = (const float*)d_in[3];
    const float* b_phase    = (const float*)d_in[4];
    float* out = (float*)d_out;

    k0_params<<<1, DD>>>(omega, alpha_raw, b_log_mag, b_phase);
    k1_localF<<<BB * NCHUNK, DD>>>(x);
    k2_scan<<<BB, DD>>>();
    k3_main<<<BB * NCHUNK, DD>>>(x, out);
}

// round 2
// speedup vs baseline: 3.9314x; 3.9314x over previous
#include <cuda_runtime.h>
#include <cstdint>

// Problem constants (fixed by the dataset).
#define BB 8
#define LL 80000
#define DD 128
#define TT 128
#define NCHUNK (LL / TT)   // 625
#define MAXW 32            // max seed window (chunks); actual wlen derived from alpha

// Scratch (no cudaMalloc allowed).
__device__ float  d_params[4 * DD];          // zr, zi, cr, ci (SoA)
__device__ float2 d_P[MAXW * DD];            // P[i] = (z^T)^i, i=0..MAXW-1 (SoA over d)
__device__ int    d_wlen[DD];                // per-d seed window length
__device__ float2 d_F[BB * NCHUNK * DD];     // per-chunk local contribution (5.1 MB)

// ---------------------------------------------------------------------------
// K0: derive per-filter parameters + z^T power table in double (runs once).
// ---------------------------------------------------------------------------
__global__ void k0_params(const float* __restrict__ omega,
                          const float* __restrict__ alpha_raw,
                          const float* __restrict__ b_log_mag,
                          const float* __restrict__ b_phase) {
    int d = threadIdx.x;
    if (d >= DD) return;
    double ar    = (double)alpha_raw[d];
    double alpha = -log1p(exp(ar));              // -softplus (alpha < 0)
    double a     = exp(alpha);
    double w     = (double)omega[d];
    double zr    = a * cos(w);
    double zi    = a * sin(w);
    double bmag  = exp((double)b_log_mag[d]);
    double ph    = (double)b_phase[d];

    d_params[0 * DD + d] = (float)zr;
    d_params[1 * DD + d] = (float)zi;
    d_params[2 * DD + d] = (float)(bmag * cos(ph));
    d_params[3 * DD + d] = (float)(bmag * sin(ph));

    // z^T and its powers
    double aT  = exp(alpha * (double)TT);
    double wT  = w * (double)TT;
    double zTr = aT * cos(wT);
    double zTi = aT * sin(wT);

    double pr = 1.0, pi = 0.0;
    for (int i = 0; i < MAXW; ++i) {
        d_P[i * DD + d] = make_float2((float)pr, (float)pi);
        double nr = pr * zTr - pi * zTi;
        double ni = pr * zTi + pi * zTr;
        pr = nr; pi = ni;
    }

    // window length: |z^T|^wl <= 1e-7  ->  wl = ceil(16.12 / (alpha*T magnitude))
    double decay = -alpha * (double)TT;          // > 0
    int wl = (int)ceil(16.12 / decay);
    if (wl < 1) wl = 1;
    if (wl > MAXW) wl = MAXW;
    d_wlen[d] = wl;
}

// ---------------------------------------------------------------------------
// K1: per (b, chunk): local recurrence from zero state -> F_j = c * acc.
// Block = 128 threads (one per d).
// ---------------------------------------------------------------------------
__global__ void k1_localF(const float* __restrict__ x) {
    int blk = blockIdx.x;
    int b = blk / NCHUNK;
    int j = blk % NCHUNK;
    int d = threadIdx.x;

    __shared__ float sx[TT];
    sx[d] = x[(size_t)b * LL + (size_t)j * TT + d];
    __syncthreads();

    float zr = d_params[0 * DD + d];
    float zi = d_params[1 * DD + d];
    float cr = d_params[2 * DD + d];
    float ci = d_params[3 * DD + d];

    float ar = 0.f, ai = 0.f;
    const float4* sx4 = (const float4*)sx;
#pragma unroll 4
    for (int u4 = 0; u4 < TT / 4; ++u4) {
        float4 xv = sx4[u4];
        float xs[4] = {xv.x, xv.y, xv.z, xv.w};
#pragma unroll
        for (int k = 0; k < 4; ++k) {
            float xu = xs[k];
            float nr = fmaf(zr, ar, fmaf(-zi, ai, xu));
            float ni = fmaf(zr, ai, zi * ar);
            ar = nr; ai = ni;
        }
    }
    float Fr = fmaf(cr, ar, -ci * ai);
    float Fi = fmaf(cr, ai,  ci * ar);
    d_F[((size_t)b * NCHUNK + j) * DD + d] = make_float2(Fr, Fi);
}

// ---------------------------------------------------------------------------
// K3: per (b, chunk): seed H from windowed sum over previous chunks' F,
// then run the recurrence over TT samples emitting power each step.
// ---------------------------------------------------------------------------
__global__ void k3_main(const float* __restrict__ x, float* __restrict__ out) {
    int blk = blockIdx.x;
    int b = blk / NCHUNK;
    int j = blk % NCHUNK;
    int d = threadIdx.x;

    __shared__ float sx[TT];
    sx[d] = x[(size_t)b * LL + (size_t)j * TT + d];
    __syncthreads();

    float zr = d_params[0 * DD + d];
    float zi = d_params[1 * DD + d];
    float cr = d_params[2 * DD + d];
    float ci = d_params[3 * DD + d];

    // Seed: S_j = sum_{i=1..W} P[i-1] (*) F[j-i]   (complex)
    float hr = 0.f, hi = 0.f;
    {
        int wl = d_wlen[d];
        if (wl > j) wl = j;
        const float2* __restrict__ Fb = d_F + (size_t)b * NCHUNK * DD + d;
#pragma unroll 4
        for (int i = 1; i <= wl; ++i) {
            float2 p = d_P[(i - 1) * DD + d];
            float2 f = Fb[(size_t)(j - i) * DD];
            hr = fmaf(p.x, f.x, hr);
            hr = fmaf(-p.y, f.y, hr);
            hi = fmaf(p.x, f.y, hi);
            hi = fmaf(p.y, f.x, hi);
        }
    }

    float* __restrict__ o = out + ((size_t)b * LL + (size_t)j * TT) * DD + d;
    const float4* sx4 = (const float4*)sx;
#pragma unroll 4
    for (int u4 = 0; u4 < TT / 4; ++u4) {
        float4 xv = sx4[u4];
        float xs[4] = {xv.x, xv.y, xv.z, xv.w};
#pragma unroll
        for (int k = 0; k < 4; ++k) {
            float xu = xs[k];
            float nr = fmaf(zr, hr, fmaf(-zi, hi, cr * xu));
            float ni = fmaf(zr, hi, fmaf( zi, hr, ci * xu));
            hr = nr; hi = ni;
            o[(size_t)(u4 * 4 + k) * DD] = fmaf(hr, hr, hi * hi);
        }
    }
}

// ---------------------------------------------------------------------------
// Launch. Inputs (metadata order): x, omega, alpha_raw, b_log_mag, b_phase, K.
// K is unused: the seed window is derived from alpha itself (tail < 1e-7).
// ---------------------------------------------------------------------------
extern "C" void kernel_launch(void* const* d_in, const int* in_sizes, int n_in,
                              void* d_out, int out_size) {
    const float* x          = (const float*)d_in[0];
    const float* omega      = (const float*)d_in[1];
    const float* alpha_raw  = (const float*)d_in[2];
    const float* b_log_mag  = (const float*)d_in[3];
    const float* b_phase    = (const float*)d_in[4];
    float* out = (float*)d_out;

    k0_params<<<1, DD>>>(omega, alpha_raw, b_log_mag, b_phase);
    k1_localF<<<BB * NCHUNK, DD>>>(x);
    k3_main<<<BB * NCHUNK, DD>>>(x, out);
}

// round 3
// speedup vs baseline: 4.3320x; 1.1019x over previous
#include <cuda_runtime.h>
#include <cstdint>

// Problem constants (fixed by the dataset).
#define BB 8
#define LL 80000
#define DD 128
#define TT 128
#define NCHUNK (LL / TT)   // 625
#define MAXW 32            // max seed window (chunks); actual wlen derived from alpha

typedef unsigned long long u64;

// Scratch (no cudaMalloc allowed).
__device__ float  d_zr[DD], d_zi[DD], d_cr[DD], d_ci[DD];
__device__ float  d_Pr[MAXW * DD], d_Pi[MAXW * DD];   // (z^T)^i, SoA over d
__device__ int    d_wlen[DD];
__device__ float2 d_F[BB * NCHUNK * DD];              // per-chunk local contribution

// ---------------- f32x2 packed helpers ----------------
__device__ __forceinline__ u64 pk2(float lo, float hi) {
    u64 r;
    asm("mov.b64 %0,{%1,%2};" : "=l"(r)
        : "r"(__float_as_uint(lo)), "r"(__float_as_uint(hi)));
    return r;
}
__device__ __forceinline__ float2 upk2(u64 v) {
    unsigned lo, hi;
    asm("mov.b64 {%0,%1},%2;" : "=r"(lo), "=r"(hi) : "l"(v));
    return make_float2(__uint_as_float(lo), __uint_as_float(hi));
}
__device__ __forceinline__ u64 fma2(u64 a, u64 b, u64 c) {
    u64 d;
    asm("fma.rn.f32x2 %0,%1,%2,%3;" : "=l"(d) : "l"(a), "l"(b), "l"(c));
    return d;
}
__device__ __forceinline__ u64 mul2(u64 a, u64 b) {
    u64 d;
    asm("mul.rn.f32x2 %0,%1,%2;" : "=l"(d) : "l"(a), "l"(b));
    return d;
}

// ---------------------------------------------------------------------------
// K0: params + power table, fully parallel. Grid = MAXW blocks x DD threads.
// Thread (i, d) computes (z_d^T)^i in double. Block 0 also writes params.
// ---------------------------------------------------------------------------
__global__ void k0_params(const float* __restrict__ omega,
                          const float* __restrict__ alpha_raw,
                          const float* __restrict__ b_log_mag,
                          const float* __restrict__ b_phase) {
    int d = threadIdx.x;
    int i = blockIdx.x;
    double ar    = (double)alpha_raw[d];
    double alpha = -log1p(exp(ar));              // -softplus (alpha < 0)
    double w     = (double)omega[d];

    double tpow = (double)TT * (double)i;
    double mag  = exp(alpha * tpow);
    double s, c;
    sincos(w * tpow, &s, &c);
    d_Pr[i * DD + d] = (float)(mag * c);
    d_Pi[i * DD + d] = (float)(mag * s);

    if (i == 0) {
        double a = exp(alpha);
        double s1, c1; sincos(w, &s1, &c1);
        d_zr[d] = (float)(a * c1);
        d_zi[d] = (float)(a * s1);
        double bmag = exp((double)b_log_mag[d]);
        double s2, c2; sincos((double)b_phase[d], &s2, &c2);
        d_cr[d] = (float)(bmag * c2);
        d_ci[d] = (float)(bmag * s2);
        // |z^T|^wl <= 1e-7
        double decay = -alpha * (double)TT;
        int wl = (int)ceil(16.12 / decay);
        wl = max(1, min(wl, MAXW));
        d_wlen[d] = wl;
    }
}

// ---------------------------------------------------------------------------
// K1: per (b, chunk): local recurrence from zero state -> F_j = c * acc.
// Block = 64 threads; each thread handles filters (2t, 2t+1) packed f32x2.
// ---------------------------------------------------------------------------
__global__ void k1_localF(const float* __restrict__ x) {
    int blk = blockIdx.x;
    int b = blk / NCHUNK;
    int j = blk % NCHUNK;
    int t = threadIdx.x;       // 0..63
    int d0 = 2 * t;

    __shared__ float2 sx[TT];  // (x, x) duplicated for packed broadcast
    const float* xp = x + (size_t)b * LL + (size_t)j * TT;
    for (int i = t; i < TT; i += 64) { float v = xp[i]; sx[i] = make_float2(v, v); }
    __syncthreads();

    float2 zr2 = *(const float2*)&d_zr[d0];
    float2 zi2 = *(const float2*)&d_zi[d0];
    float2 cr2 = *(const float2*)&d_cr[d0];
    float2 ci2 = *(const float2*)&d_ci[d0];
    u64 zr    = pk2(zr2.x, zr2.y);
    u64 zi    = pk2(zi2.x, zi2.y);
    u64 negzi = pk2(-zi2.x, -zi2.y);
    u64 cr    = pk2(cr2.x, cr2.y);
    u64 ci    = pk2(ci2.x, ci2.y);
    u64 negci = pk2(-ci2.x, -ci2.y);

    const u64* sxp = reinterpret_cast<const u64*>(sx);
    u64 ar = 0ull, ai = 0ull;    // packed (0.f, 0.f)
#pragma unroll 16
    for (int u = 0; u < TT; ++u) {
        u64 xx = sxp[u];
        u64 t1 = fma2(negzi, ai, xx);
        u64 nr = fma2(zr, ar, t1);
        u64 t2 = mul2(zi, ar);
        u64 ni = fma2(zr, ai, t2);
        ar = nr; ai = ni;
    }
    u64 Fr = fma2(negci, ai, mul2(cr, ar));
    u64 Fi = fma2(ci, ar, mul2(cr, ai));
    float2 fr = upk2(Fr), fi = upk2(Fi);
    *(float4*)&d_F[((size_t)b * NCHUNK + j) * DD + d0] =
        make_float4(fr.x, fi.x, fr.y, fi.y);
}

// ---------------------------------------------------------------------------
// K3: per (b, chunk): seed H from windowed sum over previous chunks' F,
// then recurrence over TT samples emitting |H|^2 (float2 store per pair).
// ---------------------------------------------------------------------------
__global__ void k3_main(const float* __restrict__ x, float* __restrict__ out) {
    int blk = blockIdx.x;
    int b = blk / NCHUNK;
    int j = blk % NCHUNK;
    int t = threadIdx.x;
    int d0 = 2 * t;

    __shared__ float2 sx[TT];
    const float* xp = x + (size_t)b * LL + (size_t)j * TT;
    for (int i = t; i < TT; i += 64) { float v = xp[i]; sx[i] = make_float2(v, v); }
    __syncthreads();

    float2 zr2 = *(const float2*)&d_zr[d0];
    float2 zi2 = *(const float2*)&d_zi[d0];
    float2 cr2 = *(const float2*)&d_cr[d0];
    float2 ci2 = *(const float2*)&d_ci[d0];
    u64 zr    = pk2(zr2.x, zr2.y);
    u64 zi    = pk2(zi2.x, zi2.y);
    u64 negzi = pk2(-zi2.x, -zi2.y);
    u64 cr    = pk2(cr2.x, cr2.y);
    u64 ci    = pk2(ci2.x, ci2.y);

    // Seed: S_j = sum_{i=1..wl} (z^T)^{i-1} (*) F[j-i]
    u64 hr = 0ull, hi = 0ull;
    {
        int wl = d_wlen[d0];
        if (wl > j) wl = j;
        const float2* Fb = d_F + (size_t)b * NCHUNK * DD;
        for (int i = 1; i <= wl; ++i) {
            float4 f   = *(const float4*)&Fb[(size_t)(j - i) * DD + d0];
            float2 pr2 = *(const float2*)&d_Pr[(i - 1) * DD + d0];
            float2 pi2 = *(const float2*)&d_Pi[(i - 1) * DD + d0];
            u64 Fr = pk2(f.x, f.z), Fi = pk2(f.y, f.w);
            u64 Pr = pk2(pr2.x, pr2.y);
            u64 Pi = pk2(pi2.x, pi2.y);
            u64 nPi = pk2(-pi2.x, -pi2.y);
            hr = fma2(Pr, Fr, hr);
            hr = fma2(nPi, Fi, hr);
            hi = fma2(Pr, Fi, hi);
            hi = fma2(Pi, Fr, hi);
        }
    }

    float* o = out + ((size_t)b * LL + (size_t)j * TT) * DD + d0;
    const u64* sxp = reinterpret_cast<const u64*>(sx);
#pragma unroll 16
    for (int u = 0; u < TT; ++u) {
        u64 xx  = sxp[u];
        u64 crx = mul2(cr, xx);
        u64 cix = mul2(ci, xx);
        u64 t1  = fma2(negzi, hi, crx);
        u64 nr  = fma2(zr, hr, t1);
        u64 t2  = fma2(zi, hr, cix);
        u64 ni  = fma2(zr, hi, t2);
        hr = nr; hi = ni;
        u64 pw  = fma2(hi, hi, mul2(hr, hr));
        *(float2*)(o + (size_t)u * DD) = upk2(pw);
    }
}

// ---------------------------------------------------------------------------
// Launch. Inputs (metadata order): x, omega, alpha_raw, b_log_mag, b_phase, K.
// K is unused: the seed window is derived from alpha itself (tail < 1e-7).
// ---------------------------------------------------------------------------
extern "C" void kernel_launch(void* const* d_in, const int* in_sizes, int n_in,
                              void* d_out, int out_size) {
    const float* x          = (const float*)d_in[0];
    const float* omega      = (const float*)d_in[1];
    const float* alpha_raw  = (const float*)d_in[2];
    const float* b_log_mag  = (const float*)d_in[3];
    const float* b_phase    = (const float*)d_in[4];
    float* out = (float*)d_out;

    k0_params<<<MAXW, DD>>>(omega, alpha_raw, b_log_mag, b_phase);
    k1_localF<<<BB * NCHUNK, 64>>>(x);
    k3_main<<<BB * NCHUNK, 64>>>(x, out);
}

// round 4
// speedup vs baseline: 4.6267x; 1.0680x over previous
#include <cuda_runtime.h>
#include <cstdint>

// Problem constants (fixed by the dataset).
#define BB 8
#define LL 80000
#define DD 128
#define TT 320
#define NCHUNK (LL / TT)   // 250
#define MAXW 16            // max seed window (chunks); actual wlen derived from alpha

typedef unsigned long long u64;

// Scratch (no cudaMalloc allowed).
__device__ float  d_zr[DD], d_zi[DD], d_cr[DD], d_ci[DD];
__device__ float  d_Pr[MAXW * DD], d_Pi[MAXW * DD];   // (z^T)^i, SoA over d
__device__ int    d_wlen[DD];
__device__ float2 d_F[BB * NCHUNK * DD];              // per-chunk local contribution (2 MB)

// ---------------- f32x2 packed helpers ----------------
__device__ __forceinline__ u64 pk2(float lo, float hi) {
    u64 r;
    asm("mov.b64 %0,{%1,%2};" : "=l"(r)
        : "r"(__float_as_uint(lo)), "r"(__float_as_uint(hi)));
    return r;
}
__device__ __forceinline__ float2 upk2(u64 v) {
    unsigned lo, hi;
    asm("mov.b64 {%0,%1},%2;" : "=r"(lo), "=r"(hi) : "l"(v));
    return make_float2(__uint_as_float(lo), __uint_as_float(hi));
}
__device__ __forceinline__ u64 fma2(u64 a, u64 b, u64 c) {
    u64 d;
    asm("fma.rn.f32x2 %0,%1,%2,%3;" : "=l"(d) : "l"(a), "l"(b), "l"(c));
    return d;
}
__device__ __forceinline__ u64 mul2(u64 a, u64 b) {
    u64 d;
    asm("mul.rn.f32x2 %0,%1,%2;" : "=l"(d) : "l"(a), "l"(b));
    return d;
}

// ---------------------------------------------------------------------------
// K0: params + power table, fp32 (one cheap dp range-reduction, no dp
// transcendentals). 1 block x 128 threads, ~1 us.
// ---------------------------------------------------------------------------
__global__ void k0_params(const float* __restrict__ omega,
                          const float* __restrict__ alpha_raw,
                          const float* __restrict__ b_log_mag,
                          const float* __restrict__ b_phase) {
    int d = threadIdx.x;
    float ar    = alpha_raw[d];
    float alpha = -log1pf(expf(ar));             // -softplus (alpha < 0)
    float w     = omega[d];

    float a = expf(alpha);
    float s1, c1; sincosf(w, &s1, &c1);
    d_zr[d] = a * c1;
    d_zi[d] = a * s1;

    float bm = expf(b_log_mag[d]);
    float s2, c2; sincosf(b_phase[d], &s2, &c2);
    d_cr[d] = bm * c2;
    d_ci[d] = bm * s2;

    // z^T: magnitude in fp32; phase w*T reduced mod 2pi with a few dp FMAs.
    float aT = expf(alpha * (float)TT);
    double y  = (double)w * (double)TT;
    double kq = floor(y * 0.15915494309189535);  // 1/(2*pi)
    double r  = y - kq * 6.283185307179586;
    float s3, c3; sincosf((float)r, &s3, &c3);
    float zTr = aT * c3, zTi = aT * s3;

    // window: |z^T|^wl <= 1e-7
    float decay = -alpha * (float)TT;
    int wl = (int)ceilf(16.12f / decay);
    wl = max(1, min(wl, MAXW));
    d_wlen[d] = wl;

    float pr = 1.f, pi = 0.f;
#pragma unroll
    for (int i = 0; i < MAXW; ++i) {
        d_Pr[i * DD + d] = pr;
        d_Pi[i * DD + d] = pi;
        float nr = fmaf(pr, zTr, -pi * zTi);
        float ni = fmaf(pr, zTi,  pi * zTr);
        pr = nr; pi = ni;
    }
}

// ---------------------------------------------------------------------------
// K1: per (b, chunk): local recurrence from zero state -> F_j = c * acc.
// Block = 64 threads; thread t handles filters (2t, 2t+1) packed f32x2.
// ---------------------------------------------------------------------------
__global__ void k1_localF(const float* __restrict__ x) {
    int blk = blockIdx.x;
    int b = blk / NCHUNK;
    int j = blk % NCHUNK;
    int t = threadIdx.x;       // 0..63
    int d0 = 2 * t;

    __shared__ float2 sx[TT];  // (x, x) duplicated for packed broadcast
    const float* xp = x + (size_t)b * LL + (size_t)j * TT;
    for (int i = t; i < TT; i += 64) { float v = xp[i]; sx[i] = make_float2(v, v); }
    __syncthreads();

    float2 zr2 = *(const float2*)&d_zr[d0];
    float2 zi2 = *(const float2*)&d_zi[d0];
    float2 cr2 = *(const float2*)&d_cr[d0];
    float2 ci2 = *(const float2*)&d_ci[d0];
    u64 zr    = pk2(zr2.x, zr2.y);
    u64 zi    = pk2(zi2.x, zi2.y);
    u64 negzi = pk2(-zi2.x, -zi2.y);
    u64 cr    = pk2(cr2.x, cr2.y);
    u64 ci    = pk2(ci2.x, ci2.y);
    u64 negci = pk2(-ci2.x, -ci2.y);

    const u64* sxp = reinterpret_cast<const u64*>(sx);
    u64 ar = 0ull, ai = 0ull;    // packed (0.f, 0.f)
#pragma unroll 16
    for (int u = 0; u < TT; ++u) {
        u64 xx = sxp[u];
        u64 t1 = fma2(negzi, ai, xx);
        u64 nr = fma2(zr, ar, t1);
        u64 t2 = mul2(zi, ar);
        u64 ni = fma2(zr, ai, t2);
        ar = nr; ai = ni;
    }
    u64 Fr = fma2(negci, ai, mul2(cr, ar));
    u64 Fi = fma2(ci, ar, mul2(cr, ai));
    float2 fr = upk2(Fr), fi = upk2(Fi);
    *(float4*)&d_F[((size_t)b * NCHUNK + j) * DD + d0] =
        make_float4(fr.x, fi.x, fr.y, fi.y);
}

// ---------------------------------------------------------------------------
// K3: per (b, chunk): seed H from windowed sum over previous chunks' F,
// then recurrence over TT samples emitting |H|^2 (streaming float2 stores).
// ---------------------------------------------------------------------------
__global__ void k3_main(const float* __restrict__ x, float* __restrict__ out) {
    int blk = blockIdx.x;
    int b = blk / NCHUNK;
    int j = blk % NCHUNK;
    int t = threadIdx.x;
    int d0 = 2 * t;

    __shared__ float2 sx[TT];
    const float* xp = x + (size_t)b * LL + (size_t)j * TT;
    for (int i = t; i < TT; i += 64) { float v = xp[i]; sx[i] = make_float2(v, v); }
    __syncthreads();

    float2 zr2 = *(const float2*)&d_zr[d0];
    float2 zi2 = *(const float2*)&d_zi[d0];
    float2 cr2 = *(const float2*)&d_cr[d0];
    float2 ci2 = *(const float2*)&d_ci[d0];
    u64 zr    = pk2(zr2.x, zr2.y);
    u64 zi    = pk2(zi2.x, zi2.y);
    u64 negzi = pk2(-zi2.x, -zi2.y);
    u64 cr    = pk2(cr2.x, cr2.y);
    u64 ci    = pk2(ci2.x, ci2.y);

    // Seed: S_j = sum_{i=1..wl} (z^T)^{i-1} (*) F[j-i]
    u64 hr = 0ull, hi = 0ull;
    {
        int wl = d_wlen[d0];
        if (wl > j) wl = j;
        const float2* Fb = d_F + (size_t)b * NCHUNK * DD;
        for (int i = 1; i <= wl; ++i) {
            float4 f   = *(const float4*)&Fb[(size_t)(j - i) * DD + d0];
            float2 pr2 = *(const float2*)&d_Pr[(i - 1) * DD + d0];
            float2 pi2 = *(const float2*)&d_Pi[(i - 1) * DD + d0];
            u64 Fr = pk2(f.x, f.z), Fi = pk2(f.y, f.w);
            u64 Pr = pk2(pr2.x, pr2.y);
            u64 Pi = pk2(pi2.x, pi2.y);
            u64 nPi = pk2(-pi2.x, -pi2.y);
            hr = fma2(Pr, Fr, hr);
            hr = fma2(nPi, Fi, hr);
            hi = fma2(Pr, Fi, hi);
            hi = fma2(Pi, Fr, hi);
        }
    }

    float* o = out + ((size_t)b * LL + (size_t)j * TT) * DD + d0;
    const u64* sxp = reinterpret_cast<const u64*>(sx);
#pragma unroll 16
    for (int u = 0; u < TT; ++u) {
        u64 xx  = sxp[u];
        u64 crx = mul2(cr, xx);
        u64 cix = mul2(ci, xx);
        u64 t1  = fma2(negzi, hi, crx);
        u64 nr  = fma2(zr, hr, t1);
        u64 t2  = fma2(zi, hr, cix);
        u64 ni  = fma2(zr, hi, t2);
        hr = nr; hi = ni;
        u64 pw  = fma2(hi, hi, mul2(hr, hr));
        __stcs((float2*)(o + (size_t)u * DD), upk2(pw));
    }
}

// ---------------------------------------------------------------------------
// Launch. Inputs (metadata order): x, omega, alpha_raw, b_log_mag, b_phase, K.
// K is unused: the seed window is derived from alpha itself (tail < 1e-7).
// ---------------------------------------------------------------------------
extern "C" void kernel_launch(void* const* d_in, const int* in_sizes, int n_in,
                              void* d_out, int out_size) {
    const float* x          = (const float*)d_in[0];
    const float* omega      = (const float*)d_in[1];
    const float* alpha_raw  = (const float*)d_in[2];
    const float* b_log_mag  = (const float*)d_in[3];
    const float* b_phase    = (const float*)d_in[4];
    float* out = (float*)d_out;

    k0_params<<<1, DD>>>(omega, alpha_raw, b_log_mag, b_phase);
    k1_localF<<<BB * NCHUNK, 64>>>(x);
    k3_main<<<BB * NCHUNK, 64>>>(x, out);
}

// round 5
// speedup vs baseline: 5.4410x; 1.1760x over previous
#include <cuda_runtime.h>
#include <cstdint>

// Problem constants (fixed by the dataset).
#define BB 8
#define LL 80000
#define DD 128
#define TT 640
#define NCHUNK (LL / TT)    // 125
#define MAXWARM 2048        // smem budget for warmup window (>= K=1152)

typedef unsigned long long u64;

// ---------------- f32x2 packed helpers ----------------
__device__ __forceinline__ u64 pk2(float lo, float hi) {
    u64 r;
    asm("mov.b64 %0,{%1,%2};" : "=l"(r)
        : "r"(__float_as_uint(lo)), "r"(__float_as_uint(hi)));
    return r;
}
__device__ __forceinline__ float2 upk2(u64 v) {
    unsigned lo, hi;
    asm("mov.b64 {%0,%1},%2;" : "=r"(lo), "=r"(hi) : "l"(v));
    return make_float2(__uint_as_float(lo), __uint_as_float(hi));
}
__device__ __forceinline__ u64 fma2(u64 a, u64 b, u64 c) {
    u64 d;
    asm("fma.rn.f32x2 %0,%1,%2,%3;" : "=l"(d) : "l"(a), "l"(b), "l"(c));
    return d;
}
__device__ __forceinline__ u64 mul2(u64 a, u64 b) {
    u64 d;
    asm("mul.rn.f32x2 %0,%1,%2;" : "=l"(d) : "l"(a), "l"(b));
    return d;
}

// ---------------------------------------------------------------------------
// Fused kernel. Block (b, j): warmup recurrence A = z*A + x over the K
// samples preceding the chunk (4-step unrolled, 2.5 packed ops/sample),
// then per-sample recurrence over TT samples emitting cc*|A|^2.
// 64 threads; thread t handles filters (2t, 2t+1) packed f32x2.
// ---------------------------------------------------------------------------
__global__ void __launch_bounds__(64) k_fused(
    const float* __restrict__ x,
    const float* __restrict__ omega,
    const float* __restrict__ alpha_raw,
    const float* __restrict__ b_log_mag,
    const int*   __restrict__ Kp,
    float* __restrict__ out)
{
    int blk = blockIdx.x;
    int b = blk / NCHUNK;
    int j = blk % NCHUNK;
    int t = threadIdx.x;     // 0..63
    int d0 = 2 * t;

    // Warmup length: reference's own truncation K, rounded to mult of 4.
    int K = *Kp;
    int nw = min(MAXWARM, (K + 3) & ~3);
    int eff = min(nw, j * TT);            // j*TT is a multiple of 4
    int total = eff + TT;

    __shared__ float2 sx[MAXWARM + TT];   // (x,x) duplicated for packed ops
    {
        const float* xp = x + (size_t)b * LL + (size_t)j * TT - eff;
        for (int i = t; i < total; i += 64) {
            float v = xp[i];
            sx[i] = make_float2(v, v);
        }
    }

    // Per-thread params for filters d0, d0+1 (fp32; args are small).
    float zr_s[2], zi_s[2], cc_s[2];
#pragma unroll
    for (int q = 0; q < 2; ++q) {
        int d = d0 + q;
        float alpha = -log1pf(expf(alpha_raw[d]));   // -softplus
        float a = expf(alpha);
        float s1, c1; sincosf(omega[d], &s1, &c1);
        zr_s[q] = a * c1;
        zi_s[q] = a * s1;
        cc_s[q] = expf(2.f * b_log_mag[d]);          // |c|^2 = b_mag^2
    }
    // Scalar powers z^2, z^3, z^4 per filter.
    float z2r_s[2], z2i_s[2], z3r_s[2], z3i_s[2], z4r_s[2], z4i_s[2];
#pragma unroll
    for (int q = 0; q < 2; ++q) {
        float zr = zr_s[q], zi = zi_s[q];
        z2r_s[q] = fmaf(zr, zr, -zi * zi);
        z2i_s[q] = 2.f * zr * zi;
        z3r_s[q] = fmaf(z2r_s[q], zr, -z2i_s[q] * zi);
        z3i_s[q] = fmaf(z2r_s[q], zi,  z2i_s[q] * zr);
        z4r_s[q] = fmaf(z2r_s[q], z2r_s[q], -z2i_s[q] * z2i_s[q]);
        z4i_s[q] = 2.f * z2r_s[q] * z2i_s[q];
    }
    u64 z1r  = pk2(zr_s[0],  zr_s[1]);
    u64 z1i  = pk2(zi_s[0],  zi_s[1]);
    u64 nz1i = pk2(-zi_s[0], -zi_s[1]);
    u64 z2r  = pk2(z2r_s[0], z2r_s[1]);
    u64 z2i  = pk2(z2i_s[0], z2i_s[1]);
    u64 z3r  = pk2(z3r_s[0], z3r_s[1]);
    u64 z3i  = pk2(z3i_s[0], z3i_s[1]);
    u64 z4r  = pk2(z4r_s[0], z4r_s[1]);
    u64 z4i  = pk2(z4i_s[0], z4i_s[1]);
    u64 nz4i = pk2(-z4i_s[0], -z4i_s[1]);
    u64 cc   = pk2(cc_s[0],  cc_s[1]);

    __syncthreads();

    const u64* sxp = reinterpret_cast<const u64*>(sx);

    // Warmup: A_{t+4} = z^4*A + z^3*x0 + z^2*x1 + z*x2 + x3.
    u64 ar = 0ull, ai = 0ull;
#pragma unroll 4
    for (int i = 0; i < eff; i += 4) {
        u64 x0 = sxp[i], x1 = sxp[i + 1], x2 = sxp[i + 2], x3 = sxp[i + 3];
        u64 yr = fma2(z3r, x0, fma2(z2r, x1, fma2(z1r, x2, x3)));
        u64 yi = fma2(z3i, x0, fma2(z2i, x1, mul2(z1i, x2)));
        u64 nr = fma2(z4r, ar, fma2(nz4i, ai, yr));
        u64 ni = fma2(z4r, ai, fma2(z4i, ar, yi));
        ar = nr; ai = ni;
    }

    // Main: per-sample recurrence, emit cc*|A|^2, streaming float2 stores.
    float* o = out + ((size_t)b * LL + (size_t)j * TT) * DD + d0;
    const u64* sxm = sxp + eff;
#pragma unroll 8
    for (int u = 0; u < TT; ++u) {
        u64 xx = sxm[u];
        u64 nr = fma2(z1r, ar, fma2(nz1i, ai, xx));
        u64 ni = fma2(z1r, ai, mul2(z1i, ar));
        ar = nr; ai = ni;
        u64 pw = mul2(cc, fma2(ai, ai, mul2(ar, ar)));
        __stcs((float2*)(o + (size_t)u * DD), upk2(pw));
    }
}

// ---------------------------------------------------------------------------
// Launch. Inputs (metadata order): x, omega, alpha_raw, b_log_mag, b_phase, K.
// b_phase is provably irrelevant to the output power (|c|^2 = b_mag^2).
// ---------------------------------------------------------------------------
extern "C" void kernel_launch(void* const* d_in, const int* in_sizes, int n_in,
                              void* d_out, int out_size) {
    const float* x          = (const float*)d_in[0];
    const float* omega      = (const float*)d_in[1];
    const float* alpha_raw  = (const float*)d_in[2];
    const float* b_log_mag  = (const float*)d_in[3];
    const int*   Kp         = (const int*)d_in[5];
    float* out = (float*)d_out;

    k_fused<<<BB * NCHUNK, 64>>>(x, omega, alpha_raw, b_log_mag, Kp, out);
}